// round 5
// baseline (speedup 1.0000x reference)
#include <cuda_runtime.h>
#include <cuda_bf16.h>
#include <cstdint>

#define DI __device__ __forceinline__

// ---------------- problem sizes ----------------
#define B_ROWS   4096
#define IN_F     40960
#define HID      256
#define KC       64                 // fp32 K elems per chunk
#define NCHUNK   (IN_F / KC)        // 640
#define NBLK     128                // CTAs: 8192 rows / 64
#define TPB      256
#define CHUNK_BYTES 65536           // W chunk: hi 32KB + lo 32KB
#define NSTAGE   3
#define DSMEM_BYTES (NSTAGE * CHUNK_BYTES + 1024)

// ---------------- device scratch (no cudaMalloc allowed) ----------------
// W pre-converted bf16 hi/lo, pre-swizzled: [chunk(640)][hi 32KB | lo 32KB]
__device__ __align__(128) uint8_t g_W[(size_t)NCHUNK * CHUNK_BYTES];   // 40 MB
__device__ float g_x[(size_t)B_ROWS * 2 * HID];                        // clipped concat [B, 512]

// ---------------- helpers ----------------
DI unsigned smem_u32(const void* p) {
    unsigned a;
    asm("{ .reg .u64 t; cvta.to.shared.u64 t, %1; cvt.u32.u64 %0, t; }" : "=r"(a) : "l"(p));
    return a;
}
DI unsigned sw128(unsigned off) { return off ^ ((off >> 3) & 0x70u); }

// pack two fp32 -> bf16x2 (low half = first arg)
DI unsigned pack2(float lo, float hi) {
    unsigned r;
    asm("cvt.rn.bf16x2.f32 %0, %1, %2;" : "=r"(r) : "f"(hi), "f"(lo));
    return r;
}
DI unsigned lds32(unsigned a) {
    unsigned v;
    asm volatile("ld.shared.b32 %0, [%1];" : "=r"(v) : "r"(a));
    return v;
}
DI void cp16(unsigned dst, const void* src) {
    asm volatile("cp.async.cg.shared.global [%0], [%1], 16;" :: "r"(dst), "l"(src) : "memory");
}
DI void cp_commit()  { asm volatile("cp.async.commit_group;" ::: "memory"); }
DI void cp_wait1()   { asm volatile("cp.async.wait_group 1;" ::: "memory"); }
DI void cp_wait0()   { asm volatile("cp.async.wait_group 0;" ::: "memory"); }

DI void mma_bf16(float* d, unsigned a0, unsigned a1, unsigned a2, unsigned a3,
                 unsigned b0, unsigned b1) {
    asm volatile(
        "mma.sync.aligned.m16n8k16.row.col.f32.bf16.bf16.f32 "
        "{%0,%1,%2,%3}, {%4,%5,%6,%7}, {%8,%9}, {%0,%1,%2,%3};"
        : "+f"(d[0]), "+f"(d[1]), "+f"(d[2]), "+f"(d[3])
        : "r"(a0), "r"(a1), "r"(a2), "r"(a3), "r"(b0), "r"(b1));
}

// ================= kernel 1: convert + swizzle W_ft =================
// W_ft [256][40960] fp32 -> per-chunk blocks [n(256)][k(64)] bf16 hi/lo, sw128-swizzled
__global__ void prep_w_kernel(const float* __restrict__ Wft) {
    unsigned idx = blockIdx.x * 256u + threadIdx.x;   // exactly HID*IN_F threads
    unsigned n = idx / IN_F;
    unsigned k = idx - n * IN_F;
    float w = Wft[idx];
    __nv_bfloat16 h = __float2bfloat16(w);
    float hf = __bfloat162float(h);
    __nv_bfloat16 l = __float2bfloat16(w - hf);
    unsigned c  = k >> 6;
    unsigned kk = k & 63u;
    size_t base = (size_t)c * CHUNK_BYTES;
    unsigned sw = sw128(n * 128u + kk * 2u);
    *(__nv_bfloat16*)(g_W + base + sw)         = h;
    *(__nv_bfloat16*)(g_W + base + 32768 + sw) = l;
}

// ================= kernel 2: feature-transformer GEMM (mma.sync bf16, 3-term) ======
// C[8192,256] = A[8192,40960] @ W^T ; CTA: 64 rows x 256 cols, 8 warps (warp: 16 x 128)
struct AFrags { unsigned h[4]; unsigned l[4]; };

DI void loadA(float2 buf[4], const float* pr0, const float* pr1, unsigned kg) {
    buf[0] = *(const float2*)(pr0 + kg);
    buf[1] = *(const float2*)(pr1 + kg);
    buf[2] = *(const float2*)(pr0 + kg + 8);
    buf[3] = *(const float2*)(pr1 + kg + 8);
}

DI void convertA(const float2 buf[4], AFrags& f) {
#pragma unroll
    for (int q = 0; q < 4; q++) {
        unsigned h = pack2(buf[q].x, buf[q].y);
        float lx = buf[q].x - __uint_as_float(h << 16);
        float ly = buf[q].y - __uint_as_float(h & 0xFFFF0000u);
        f.h[q] = h;
        f.l[q] = pack2(lx, ly);
    }
}

DI void do_step(unsigned stg, unsigned sw0, unsigned sw1,
                const float2 cur[4], float acc[16][4]) {
    AFrags f;
    convertA(cur, f);
    unsigned ad0 = stg + sw0;
    unsigned ad1 = stg + sw1;
#pragma unroll
    for (int j = 0; j < 16; j++) {
        unsigned bh0 = lds32(ad0);
        unsigned bh1 = lds32(ad1);
        unsigned bl0 = lds32(ad0 + 32768);
        unsigned bl1 = lds32(ad1 + 32768);
        mma_bf16(acc[j], f.h[0], f.h[1], f.h[2], f.h[3], bh0, bh1);  // hi*whi
        mma_bf16(acc[j], f.h[0], f.h[1], f.h[2], f.h[3], bl0, bl1);  // hi*wlo
        mma_bf16(acc[j], f.l[0], f.l[1], f.l[2], f.l[3], bh0, bh1);  // lo*whi
        ad0 += 1024;
        ad1 += 1024;
    }
}

__global__ void __launch_bounds__(TPB, 1)
ft_gemm_kernel(const float* __restrict__ wfeat, const float* __restrict__ bfeat) {
    extern __shared__ uint8_t dsm[];
    const int tid = threadIdx.x;
    const int w   = tid >> 5;
    const int l   = tid & 31;
    const int b   = blockIdx.x;

    const bool white = (b < NBLK / 2);
    const float* feat = white ? (wfeat + (size_t)b * 64 * IN_F)
                              : (bfeat + (size_t)(b - NBLK / 2) * 64 * IN_F);

    const int wm = (w >> 1) * 16;       // warp M offset within 64
    const int wn = (w & 1) * 128;       // warp N offset within 256

    const unsigned sbase = (smem_u32(dsm) + 1023u) & ~1023u;

    // A fragment row pointers (rows fixed for whole K loop)
    const float* pr0 = feat + (size_t)(wm + (l >> 2)) * IN_F + (l & 3) * 2;
    const float* pr1 = pr0 + (size_t)8 * IN_F;

    float acc[16][4];
#pragma unroll
    for (int j = 0; j < 16; j++)
#pragma unroll
        for (int q = 0; q < 4; q++) acc[j][q] = 0.0f;

    // per-step swizzled B offsets (depend only on lane + step)
    unsigned swb0[4], swb1[4];
#pragma unroll
    for (int s = 0; s < 4; s++) {
        unsigned base = (unsigned)(wn + (l >> 2)) * 128u + (unsigned)s * 32u + (l & 3) * 4u;
        swb0[s] = sw128(base);
        swb1[s] = sw128(base + 16u);
    }

    // W copy: 256 threads x 16 x 16B = 64 KB per chunk
    auto copyW = [&](int c) {
        const uint8_t* src = g_W + (size_t)c * CHUNK_BYTES + tid * 16;
        unsigned dst = sbase + (unsigned)(c % NSTAGE) * CHUNK_BYTES + tid * 16;
#pragma unroll
        for (int i = 0; i < 16; i++) cp16(dst + i * 4096, src + i * 4096);
        cp_commit();
    };

    copyW(0);
    copyW(1);

    float2 bufA[4], bufB[4];
    loadA(bufA, pr0, pr1, 0);

    for (int c = 0; c < NCHUNK; c++) {
        cp_wait1();
        __syncthreads();
        const unsigned stg = sbase + (unsigned)(c % NSTAGE) * CHUNK_BYTES;
        const unsigned kg = (unsigned)c * KC;
        const unsigned kn = (c + 1 < NCHUNK) ? (unsigned)(c + 1) * KC : 0u;

        loadA(bufB, pr0, pr1, kg + 16);
        do_step(stg, swb0[0], swb1[0], bufA, acc);
        loadA(bufA, pr0, pr1, kg + 32);
        do_step(stg, swb0[1], swb1[1], bufB, acc);
        loadA(bufB, pr0, pr1, kg + 48);
        do_step(stg, swb0[2], swb1[2], bufA, acc);
        loadA(bufA, pr0, pr1, kn);
        do_step(stg, swb0[3], swb1[3], bufB, acc);

        if (c + 2 < NCHUNK) copyW(c + 2);
    }
    cp_wait0();

    // ---- epilogue: clip to [0,1], write concat layout g_x[B,512] ----
    const int rbase = (white ? b : b - NBLK / 2) * 64 + wm + (l >> 2);
    float* xbase = g_x + (white ? 0 : HID);
#pragma unroll
    for (int j = 0; j < 16; j++) {
        const int col = wn + j * 8 + (l & 3) * 2;
        float2 v0, v1;
        v0.x = fminf(fmaxf(acc[j][0], 0.0f), 1.0f);
        v0.y = fminf(fmaxf(acc[j][1], 0.0f), 1.0f);
        v1.x = fminf(fmaxf(acc[j][2], 0.0f), 1.0f);
        v1.y = fminf(fmaxf(acc[j][3], 0.0f), 1.0f);
        *(float2*)(xbase + (size_t)rbase * 512 + col)       = v0;
        *(float2*)(xbase + (size_t)(rbase + 8) * 512 + col) = v1;
    }
}

// ================= kernel 3: MLP 512 -> 32 -> 32 -> 1 (warp per row) =================
__global__ void mlp_kernel(const float* __restrict__ W1, const float* __restrict__ b1,
                           const float* __restrict__ W2, const float* __restrict__ b2,
                           const float* __restrict__ W3, const float* __restrict__ b3,
                           const float* __restrict__ stm, float* __restrict__ out) {
    const int warp = (blockIdx.x * blockDim.x + threadIdx.x) >> 5;
    const int lid  = threadIdx.x & 31;
    if (warp >= B_ROWS) return;
    const float* xr = g_x + (size_t)warp * 512;

    float xv[16];
#pragma unroll
    for (int i = 0; i < 16; i++) xv[i] = xr[lid + 32 * i];

    float h1 = 0.0f;
#pragma unroll
    for (int j = 0; j < 32; j++) {
        const float* wrow = W1 + j * 512;
        float a = 0.0f;
#pragma unroll
        for (int i = 0; i < 16; i++) a += xv[i] * wrow[lid + 32 * i];
#pragma unroll
        for (int off = 16; off > 0; off >>= 1) a += __shfl_xor_sync(0xFFFFFFFFu, a, off);
        a = fmaxf(a + b1[j], 0.0f);
        if (lid == j) h1 = a;
    }

    float a2 = b2[lid];
#pragma unroll
    for (int k = 0; k < 32; k++)
        a2 += __shfl_sync(0xFFFFFFFFu, h1, k) * W2[lid * 32 + k];
    float h2 = fmaxf(a2, 0.0f);

    float v = h2 * W3[lid];
#pragma unroll
    for (int off = 16; off > 0; off >>= 1) v += __shfl_xor_sync(0xFFFFFFFFu, v, off);

    if (lid == 0) out[warp] = (v + b3[0]) * stm[warp];
}

// ================= host launcher =================
extern "C" void kernel_launch(void* const* d_in, const int* in_sizes, int n_in,
                              void* d_out, int out_size) {
    const float* wfeat = (const float*)d_in[0];
    const float* bfeat = (const float*)d_in[1];
    const float* stm   = (const float*)d_in[2];
    const float* Wft   = (const float*)d_in[3];
    const float* W1    = (const float*)d_in[4];
    const float* b1    = (const float*)d_in[5];
    const float* W2    = (const float*)d_in[6];
    const float* b2    = (const float*)d_in[7];
    const float* W3    = (const float*)d_in[8];
    const float* b3    = (const float*)d_in[9];

    static bool attr_set = false;
    if (!attr_set) {
        cudaFuncSetAttribute(ft_gemm_kernel,
                             cudaFuncAttributeMaxDynamicSharedMemorySize, DSMEM_BYTES);
        attr_set = true;
    }

    prep_w_kernel<<<(HID * IN_F) / 256, 256>>>(Wft);
    ft_gemm_kernel<<<NBLK, TPB, DSMEM_BYTES>>>(wfeat, bfeat);
    mlp_kernel<<<(B_ROWS * 32) / 256, 256>>>(W1, b1, W2, b2, W3, b3, stm, (float*)d_out);
}

// round 6
// speedup vs baseline: 1.0064x; 1.0064x over previous
#include <cuda_runtime.h>
#include <cuda_bf16.h>
#include <cstdint>

#define DI __device__ __forceinline__

// ---------------- problem sizes ----------------
#define B_ROWS   4096
#define IN_F     40960
#define HID      256
#define KC       64                 // fp32 K elems per chunk
#define NCHUNK   (IN_F / KC)        // 640
#define NBLK     128                // CTAs: 8192 rows / 64
#define TPB      256
#define CHUNK_BYTES 65536           // W chunk: hi 32KB + lo 32KB
#define NSTAGE   3
#define DSMEM_BYTES (NSTAGE * CHUNK_BYTES + 1024)

// ---------------- device scratch (no cudaMalloc allowed) ----------------
// W pre-converted bf16 hi/lo, pre-swizzled: [chunk(640)][hi 32KB | lo 32KB]
__device__ __align__(128) uint8_t g_W[(size_t)NCHUNK * CHUNK_BYTES];   // 40 MB
__device__ float g_x[(size_t)B_ROWS * 2 * HID];                        // clipped concat [B, 512]

// ---------------- helpers ----------------
DI unsigned smem_u32(const void* p) {
    unsigned a;
    asm("{ .reg .u64 t; cvta.to.shared.u64 t, %1; cvt.u32.u64 %0, t; }" : "=r"(a) : "l"(p));
    return a;
}
DI unsigned sw128(unsigned off) { return off ^ ((off >> 3) & 0x70u); }

// pack two fp32 -> bf16x2 (first arg -> low half)
DI unsigned pack2(float lo, float hi) {
    unsigned r;
    asm("cvt.rn.bf16x2.f32 %0, %1, %2;" : "=r"(r) : "f"(hi), "f"(lo));
    return r;
}
DI unsigned lds32(unsigned a) {
    unsigned v;
    asm volatile("ld.shared.b32 %0, [%1];" : "=r"(v) : "r"(a));
    return v;
}
DI void cp16(unsigned dst, const void* src) {
    asm volatile("cp.async.cg.shared.global [%0], [%1], 16;" :: "r"(dst), "l"(src) : "memory");
}
DI void cp_commit()  { asm volatile("cp.async.commit_group;" ::: "memory"); }
DI void cp_wait1()   { asm volatile("cp.async.wait_group 1;" ::: "memory"); }
DI void cp_wait0()   { asm volatile("cp.async.wait_group 0;" ::: "memory"); }

DI void mma_bf16(float* d, unsigned a0, unsigned a1, unsigned a2, unsigned a3,
                 unsigned b0, unsigned b1) {
    asm volatile(
        "mma.sync.aligned.m16n8k16.row.col.f32.bf16.bf16.f32 "
        "{%0,%1,%2,%3}, {%4,%5,%6,%7}, {%8,%9}, {%0,%1,%2,%3};"
        : "+f"(d[0]), "+f"(d[1]), "+f"(d[2]), "+f"(d[3])
        : "r"(a0), "r"(a1), "r"(a2), "r"(a3), "r"(b0), "r"(b1));
}

// ================= kernel 1: convert + swizzle W_ft =================
// W_ft [256][40960] fp32 -> per-chunk blocks [n(256)][k(64)] bf16 hi/lo, sw128-swizzled
__global__ void prep_w_kernel(const float* __restrict__ Wft) {
    unsigned idx = blockIdx.x * 256u + threadIdx.x;   // exactly HID*IN_F threads
    unsigned n = idx / IN_F;
    unsigned k = idx - n * IN_F;
    float w = Wft[idx];
    __nv_bfloat16 h = __float2bfloat16(w);
    float hf = __bfloat162float(h);
    __nv_bfloat16 l = __float2bfloat16(w - hf);
    unsigned c  = k >> 6;
    unsigned kk = k & 63u;
    size_t base = (size_t)c * CHUNK_BYTES;
    unsigned sw = sw128(n * 128u + kk * 2u);
    *(__nv_bfloat16*)(g_W + base + sw)         = h;
    *(__nv_bfloat16*)(g_W + base + 32768 + sw) = l;
}

// ================= kernel 2: feature-transformer GEMM (mma.sync bf16, 3-term) ======
// C[8192,256] = A[8192,40960] @ W^T
// CTA tile: 64 rows x 256 cols, 8 warps as 2 M-groups x 4 N-groups -> warp 32M x 64N
struct AFrags { unsigned h[8]; unsigned l[8]; };

// 4 row pointers (rows r, r+8, r+16, r+24), two k-halves each -> 8 float2
DI void loadA(float2 buf[8], const float* const pr[4], unsigned kg) {
#pragma unroll
    for (int r = 0; r < 4; r++) {
        buf[2 * r]     = *(const float2*)(pr[r] + kg);
        buf[2 * r + 1] = *(const float2*)(pr[r] + kg + 8);
    }
}

DI void convertA(const float2 buf[8], AFrags& f) {
    // m-tile 0 uses rows (r, r+8) = pr[0], pr[1]; m-tile 1 uses pr[2], pr[3].
    // frag order per tile: {row@k, row+8@k, row@k+8, row+8@k+8}
#pragma unroll
    for (int t = 0; t < 2; t++) {
        const float2* b = buf + 4 * t;
        // b[0]=pr0@k  b[1]=pr0@k+8  b[2]=pr1@k  b[3]=pr1@k+8
        unsigned o = 4 * t;
        float2 q0 = b[0], q1 = b[2], q2 = b[1], q3 = b[3];
        unsigned h0 = pack2(q0.x, q0.y);
        unsigned h1 = pack2(q1.x, q1.y);
        unsigned h2 = pack2(q2.x, q2.y);
        unsigned h3 = pack2(q3.x, q3.y);
        f.h[o + 0] = h0; f.h[o + 1] = h1; f.h[o + 2] = h2; f.h[o + 3] = h3;
        f.l[o + 0] = pack2(q0.x - __uint_as_float(h0 << 16),
                           q0.y - __uint_as_float(h0 & 0xFFFF0000u));
        f.l[o + 1] = pack2(q1.x - __uint_as_float(h1 << 16),
                           q1.y - __uint_as_float(h1 & 0xFFFF0000u));
        f.l[o + 2] = pack2(q2.x - __uint_as_float(h2 << 16),
                           q2.y - __uint_as_float(h2 & 0xFFFF0000u));
        f.l[o + 3] = pack2(q3.x - __uint_as_float(h3 << 16),
                           q3.y - __uint_as_float(h3 & 0xFFFF0000u));
    }
}

// one k16 step: 8 n8-tiles x (2 m-tiles x 3 terms)
DI void do_step(unsigned stg, unsigned sw0, unsigned sw1,
                const float2 cur[8], float acc[2][8][4]) {
    AFrags f;
    convertA(cur, f);
    unsigned ad0 = stg + sw0;
    unsigned ad1 = stg + sw1;
#pragma unroll
    for (int j = 0; j < 8; j++) {
        unsigned bh0 = lds32(ad0);
        unsigned bh1 = lds32(ad1);
        unsigned bl0 = lds32(ad0 + 32768);
        unsigned bl1 = lds32(ad1 + 32768);
        mma_bf16(acc[0][j], f.h[0], f.h[1], f.h[2], f.h[3], bh0, bh1);  // hi*whi
        mma_bf16(acc[0][j], f.h[0], f.h[1], f.h[2], f.h[3], bl0, bl1);  // hi*wlo
        mma_bf16(acc[0][j], f.l[0], f.l[1], f.l[2], f.l[3], bh0, bh1);  // lo*whi
        mma_bf16(acc[1][j], f.h[4], f.h[5], f.h[6], f.h[7], bh0, bh1);
        mma_bf16(acc[1][j], f.h[4], f.h[5], f.h[6], f.h[7], bl0, bl1);
        mma_bf16(acc[1][j], f.l[4], f.l[5], f.l[6], f.l[7], bh0, bh1);
        ad0 += 1024;    // next n8 row group (+8 rows * 128B); swizzle-invariant
        ad1 += 1024;
    }
}

__global__ void __launch_bounds__(TPB, 1)
ft_gemm_kernel(const float* __restrict__ wfeat, const float* __restrict__ bfeat) {
    extern __shared__ uint8_t dsm[];
    const int tid = threadIdx.x;
    const int w   = tid >> 5;
    const int l   = tid & 31;
    const int b   = blockIdx.x;

    const bool white = (b < NBLK / 2);
    const float* feat = white ? (wfeat + (size_t)b * 64 * IN_F)
                              : (bfeat + (size_t)(b - NBLK / 2) * 64 * IN_F);

    const int wm = (w >> 2) * 32;       // warp M offset within 64 (2 groups)
    const int wn = (w & 3) * 64;        // warp N offset within 256 (4 groups)

    const unsigned sbase = (smem_u32(dsm) + 1023u) & ~1023u;

    // A row pointers: rows wm + (l>>2) + {0,8,16,24}
    const float* pr[4];
    pr[0] = feat + (size_t)(wm + (l >> 2)) * IN_F + (l & 3) * 2;
    pr[1] = pr[0] + (size_t)8  * IN_F;
    pr[2] = pr[0] + (size_t)16 * IN_F;
    pr[3] = pr[0] + (size_t)24 * IN_F;

    float acc[2][8][4];
#pragma unroll
    for (int t = 0; t < 2; t++)
#pragma unroll
        for (int j = 0; j < 8; j++)
#pragma unroll
            for (int q = 0; q < 4; q++) acc[t][j][q] = 0.0f;

    // per-step swizzled B offsets for n-row (wn + l>>2), k bytes s*32 + (l&3)*4
    unsigned swb0[4], swb1[4];
#pragma unroll
    for (int s = 0; s < 4; s++) {
        unsigned base = (unsigned)(wn + (l >> 2)) * 128u + (unsigned)s * 32u + (l & 3) * 4u;
        swb0[s] = sw128(base);
        swb1[s] = sw128(base + 16u);
    }

    // W copy: 256 threads x 16 x 16B = 64 KB per chunk
    auto copyW = [&](int c) {
        const uint8_t* src = g_W + (size_t)c * CHUNK_BYTES + tid * 16;
        unsigned dst = sbase + (unsigned)(c % NSTAGE) * CHUNK_BYTES + tid * 16;
#pragma unroll
        for (int i = 0; i < 16; i++) cp16(dst + i * 4096, src + i * 4096);
        cp_commit();
    };

    copyW(0);
    copyW(1);

    float2 bufA[8], bufB[8];
    loadA(bufA, pr, 0);

    for (int c = 0; c < NCHUNK; c++) {
        cp_wait1();
        __syncthreads();
        const unsigned stg = sbase + (unsigned)(c % NSTAGE) * CHUNK_BYTES;
        const unsigned kg = (unsigned)c * KC;
        const unsigned kn = (c + 1 < NCHUNK) ? (unsigned)(c + 1) * KC : 0u;

        loadA(bufB, pr, kg + 16);
        do_step(stg, swb0[0], swb1[0], bufA, acc);
        loadA(bufA, pr, kg + 32);
        do_step(stg, swb0[1], swb1[1], bufB, acc);
        loadA(bufB, pr, kg + 48);
        do_step(stg, swb0[2], swb1[2], bufA, acc);
        loadA(bufA, pr, kn);
        do_step(stg, swb0[3], swb1[3], bufB, acc);

        if (c + 2 < NCHUNK) copyW(c + 2);
    }
    cp_wait0();

    // ---- epilogue: clip to [0,1], write concat layout g_x[B,512] ----
    const int rbase = (white ? b : b - NBLK / 2) * 64 + wm + (l >> 2);
    float* xbase = g_x + (white ? 0 : HID);
#pragma unroll
    for (int t = 0; t < 2; t++) {
        const int r0 = rbase + t * 16;
#pragma unroll
        for (int j = 0; j < 8; j++) {
            const int col = wn + j * 8 + (l & 3) * 2;
            float2 v0, v1;
            v0.x = fminf(fmaxf(acc[t][j][0], 0.0f), 1.0f);
            v0.y = fminf(fmaxf(acc[t][j][1], 0.0f), 1.0f);
            v1.x = fminf(fmaxf(acc[t][j][2], 0.0f), 1.0f);
            v1.y = fminf(fmaxf(acc[t][j][3], 0.0f), 1.0f);
            *(float2*)(xbase + (size_t)r0 * 512 + col)       = v0;
            *(float2*)(xbase + (size_t)(r0 + 8) * 512 + col) = v1;
        }
    }
}

// ================= kernel 3: MLP 512 -> 32 -> 32 -> 1 (warp per row) =================
__global__ void mlp_kernel(const float* __restrict__ W1, const float* __restrict__ b1,
                           const float* __restrict__ W2, const float* __restrict__ b2,
                           const float* __restrict__ W3, const float* __restrict__ b3,
                           const float* __restrict__ stm, float* __restrict__ out) {
    const int warp = (blockIdx.x * blockDim.x + threadIdx.x) >> 5;
    const int lid  = threadIdx.x & 31;
    if (warp >= B_ROWS) return;
    const float* xr = g_x + (size_t)warp * 512;

    float xv[16];
#pragma unroll
    for (int i = 0; i < 16; i++) xv[i] = xr[lid + 32 * i];

    float h1 = 0.0f;
#pragma unroll
    for (int j = 0; j < 32; j++) {
        const float* wrow = W1 + j * 512;
        float a = 0.0f;
#pragma unroll
        for (int i = 0; i < 16; i++) a += xv[i] * wrow[lid + 32 * i];
#pragma unroll
        for (int off = 16; off > 0; off >>= 1) a += __shfl_xor_sync(0xFFFFFFFFu, a, off);
        a = fmaxf(a + b1[j], 0.0f);
        if (lid == j) h1 = a;
    }

    float a2 = b2[lid];
#pragma unroll
    for (int k = 0; k < 32; k++)
        a2 += __shfl_sync(0xFFFFFFFFu, h1, k) * W2[lid * 32 + k];
    float h2 = fmaxf(a2, 0.0f);

    float v = h2 * W3[lid];
#pragma unroll
    for (int off = 16; off > 0; off >>= 1) v += __shfl_xor_sync(0xFFFFFFFFu, v, off);

    if (lid == 0) out[warp] = (v + b3[0]) * stm[warp];
}

// ================= host launcher =================
extern "C" void kernel_launch(void* const* d_in, const int* in_sizes, int n_in,
                              void* d_out, int out_size) {
    const float* wfeat = (const float*)d_in[0];
    const float* bfeat = (const float*)d_in[1];
    const float* stm   = (const float*)d_in[2];
    const float* Wft   = (const float*)d_in[3];
    const float* W1    = (const float*)d_in[4];
    const float* b1    = (const float*)d_in[5];
    const float* W2    = (const float*)d_in[6];
    const float* b2    = (const float*)d_in[7];
    const float* W3    = (const float*)d_in[8];
    const float* b3    = (const float*)d_in[9];

    static bool attr_set = false;
    if (!attr_set) {
        cudaFuncSetAttribute(ft_gemm_kernel,
                             cudaFuncAttributeMaxDynamicSharedMemorySize, DSMEM_BYTES);
        attr_set = true;
    }

    prep_w_kernel<<<(HID * IN_F) / 256, 256>>>(Wft);
    ft_gemm_kernel<<<NBLK, TPB, DSMEM_BYTES>>>(wfeat, bfeat);
    mlp_kernel<<<(B_ROWS * 32) / 256, 256>>>(W1, b1, W2, b2, W3, b3, stm, (float*)d_out);
}

// round 9
// speedup vs baseline: 1.0080x; 1.0015x over previous
#include <cuda_runtime.h>
#include <cuda_bf16.h>
#include <cstdint>

#define DI __device__ __forceinline__

// ---------------- problem sizes ----------------
#define B_ROWS   4096
#define IN_F     40960
#define HID      256
#define KC       64                 // fp32 K elems per chunk
#define NCHUNK   (IN_F / KC)        // 640
#define NBLK     128                // CTAs: 8192 rows / 64
#define TPB      256
#define WCHUNK_BYTES 65536          // W chunk: fragment-interleaved hi+lo

// A smem staging: 64 rows x 144B (128B data + 16B pad) per hi / lo block
#define AROWB    144
#define ABLK     (64 * AROWB)       // 9216 bytes (one of hi/lo)
#define ASTAGE   (2 * ABLK)         // 18432 bytes
#define SM_W0    0
#define SM_A0    (2 * WCHUNK_BYTES) // 131072
#define DSMEM_BYTES (2 * WCHUNK_BYTES + 2 * ASTAGE + 1024)  // ~169 KB

// ---------------- device scratch ----------------
// W fragment-interleaved: [chunk][wn_group(4)][ (j*4+s)*512 + lane*16 ] = {bh0,bh1,bl0,bl1}
__device__ __align__(128) uint8_t g_W[(size_t)NCHUNK * WCHUNK_BYTES];   // 40 MB
__device__ float g_x[(size_t)B_ROWS * 2 * HID];                         // clipped concat [B, 512]

// ---------------- helpers ----------------
DI unsigned smem_u32(const void* p) {
    unsigned a;
    asm("{ .reg .u64 t; cvta.to.shared.u64 t, %1; cvt.u32.u64 %0, t; }" : "=r"(a) : "l"(p));
    return a;
}
// pack two fp32 -> bf16x2 (first arg -> LOW half)
DI unsigned pack2(float lo, float hi) {
    unsigned r;
    asm("cvt.rn.bf16x2.f32 %0, %1, %2;" : "=r"(r) : "f"(hi), "f"(lo));
    return r;
}
DI unsigned lds32(unsigned a) {
    unsigned v;
    asm volatile("ld.shared.b32 %0, [%1];" : "=r"(v) : "r"(a));
    return v;
}
DI uint4 lds128(unsigned a) {
    uint4 v;
    asm volatile("ld.shared.v4.b32 {%0,%1,%2,%3}, [%4];"
                 : "=r"(v.x), "=r"(v.y), "=r"(v.z), "=r"(v.w) : "r"(a));
    return v;
}
DI void sts64(unsigned a, unsigned x, unsigned y) {
    asm volatile("st.shared.v2.b32 [%0], {%1, %2};" :: "r"(a), "r"(x), "r"(y) : "memory");
}
DI void cp16(unsigned dst, const void* src) {
    asm volatile("cp.async.cg.shared.global [%0], [%1], 16;" :: "r"(dst), "l"(src) : "memory");
}
DI void cp_commit()  { asm volatile("cp.async.commit_group;" ::: "memory"); }
DI void cp_wait1()   { asm volatile("cp.async.wait_group 1;" ::: "memory"); }
DI void cp_wait0()   { asm volatile("cp.async.wait_group 0;" ::: "memory"); }

DI void mma_bf16(float* d, unsigned a0, unsigned a1, unsigned a2, unsigned a3,
                 unsigned b0, unsigned b1) {
    asm volatile(
        "mma.sync.aligned.m16n8k16.row.col.f32.bf16.bf16.f32 "
        "{%0,%1,%2,%3}, {%4,%5,%6,%7}, {%8,%9}, {%0,%1,%2,%3};"
        : "+f"(d[0]), "+f"(d[1]), "+f"(d[2]), "+f"(d[3])
        : "r"(a0), "r"(a1), "r"(a2), "r"(a3), "r"(b0), "r"(b1));
}

// ================= kernel 1: convert W_ft into fragment-interleaved layout ==========
// one thread per 16B output unit: (chunk, wn_group, j, s, lane)
__global__ void prep_w_kernel(const float* __restrict__ Wft) {
    unsigned g    = blockIdx.x * 256u + threadIdx.x;   // 640*4096 threads
    unsigned lane = g & 31u;
    unsigned s    = (g >> 5) & 3u;
    unsigned j    = (g >> 7) & 7u;
    unsigned wg   = (g >> 10) & 3u;
    unsigned c    = g >> 12;

    unsigned n = wg * 64u + j * 8u + (lane >> 2);
    unsigned k = c * 64u + s * 16u + (lane & 3u) * 2u;
    const float* src = Wft + (size_t)n * IN_F + k;
    float w0 = src[0], w1 = src[1], w8 = src[8], w9 = src[9];

    unsigned bh0 = pack2(w0, w1);
    unsigned bh1 = pack2(w8, w9);
    float l0 = w0 - __uint_as_float(bh0 << 16);
    float l1 = w1 - __uint_as_float(bh0 & 0xFFFF0000u);
    float l8 = w8 - __uint_as_float(bh1 << 16);
    float l9 = w9 - __uint_as_float(bh1 & 0xFFFF0000u);
    unsigned bl0 = pack2(l0, l1);
    unsigned bl1 = pack2(l8, l9);

    uint4 v = make_uint4(bh0, bh1, bl0, bl1);
    *(uint4*)(g_W + (size_t)c * WCHUNK_BYTES + wg * 16384u + (j * 4u + s) * 512u + lane * 16u) = v;
}

// ================= kernel 2: feature-transformer GEMM (mma.sync bf16, 3-term) ======
// C[8192,256] = A @ W^T; CTA 64 rows x 256 cols, warp tile 32M x 64N
__global__ void __launch_bounds__(TPB, 1)
ft_gemm_kernel(const float* __restrict__ wfeat, const float* __restrict__ bfeat) {
    extern __shared__ uint8_t dsm[];
    const int tid = threadIdx.x;
    const int w   = tid >> 5;
    const int l   = tid & 31;
    const int b   = blockIdx.x;

    const bool white = (b < NBLK / 2);
    const float* feat = white ? (wfeat + (size_t)b * 64 * IN_F)
                              : (bfeat + (size_t)(b - NBLK / 2) * 64 * IN_F);

    const int mg  = w >> 2;             // M group (0,1): rows mg*32..+31
    const int wng = w & 3;              // N group (0..3): cols wng*64..+63

    const unsigned sbase = (smem_u32(dsm) + 1023u) & ~1023u;
    const unsigned Wst[2] = { sbase + SM_W0, sbase + SM_W0 + WCHUNK_BYTES };
    const unsigned Ast[2] = { sbase + SM_A0, sbase + SM_A0 + ASTAGE };

    // ---- A coalesced load mapping: li = i*256+tid; row=li>>4, quad=li&15 ----
    const float* aptr[4];
    unsigned stsoff[4];
#pragma unroll
    for (int i = 0; i < 4; i++) {
        unsigned li = (unsigned)(i * 256 + tid);
        aptr[i]   = feat + (size_t)(li >> 4) * IN_F + (li & 15u) * 4u;
        stsoff[i] = (li >> 4) * AROWB + (li & 15u) * 8u;
    }

    // ---- A fragment LDS base offset: row mg*32 + (l>>2), k-pair (l&3) ----
    const unsigned aoff = (unsigned)(mg * 32 + (l >> 2)) * AROWB + (unsigned)(l & 3) * 4u;

    float acc[2][8][4];
#pragma unroll
    for (int t = 0; t < 2; t++)
#pragma unroll
        for (int j = 0; j < 8; j++)
#pragma unroll
            for (int q = 0; q < 4; q++) acc[t][j][q] = 0.0f;

    // W copy: 256 threads x 16 x 16B = 64 KB per chunk
    auto copyW = [&](int c, int st) {
        const uint8_t* src = g_W + (size_t)c * WCHUNK_BYTES + tid * 16;
        unsigned dst = Wst[st] + tid * 16;
#pragma unroll
        for (int i = 0; i < 16; i++) cp16(dst + i * 4096, src + i * 4096);
        cp_commit();
    };

    // convert + STS one chunk of A (16 floats in av[]) into stage st
    auto cvtSTS = [&](const float4 av[4], int st) {
        unsigned hi = Ast[st];
        unsigned lo = Ast[st] + ABLK;
#pragma unroll
        for (int i = 0; i < 4; i++) {
            float4 f = av[i];
            unsigned h0 = pack2(f.x, f.y);
            unsigned h1 = pack2(f.z, f.w);
            float lx = f.x - __uint_as_float(h0 << 16);
            float ly = f.y - __uint_as_float(h0 & 0xFFFF0000u);
            float lz = f.z - __uint_as_float(h1 << 16);
            float lw = f.w - __uint_as_float(h1 & 0xFFFF0000u);
            sts64(hi + stsoff[i], h0, h1);
            sts64(lo + stsoff[i], pack2(lx, ly), pack2(lz, lw));
        }
    };

    // ---- prologue ----
    float4 av[4];
#pragma unroll
    for (int i = 0; i < 4; i++) av[i] = *(const float4*)(aptr[i]);
    cvtSTS(av, 0);
    copyW(0, 0);
    copyW(1, 1);
    __syncthreads();

    for (int c = 0; c < NCHUNK; c++) {
        // load next chunk's A early (hidden under compute)
        if (c + 1 < NCHUNK) {
#pragma unroll
            for (int i = 0; i < 4; i++)
                av[i] = *(const float4*)(aptr[i] + (size_t)(c + 1) * KC);
        }
        if (c + 1 < NCHUNK) cp_wait1(); else cp_wait0();
        __syncthreads();   // W(c) visible to all; A stage (c&1) ready

        const unsigned aS = Ast[c & 1];
        const unsigned wS = Wst[c & 1] + (unsigned)wng * 16384u + (unsigned)l * 16u;

#pragma unroll
        for (int s = 0; s < 4; s++) {
            unsigned ab = aS + aoff + (unsigned)s * 32u;
            unsigned ah[2][4], al[2][4];
#pragma unroll
            for (int t = 0; t < 2; t++) {
                unsigned base = ab + (unsigned)t * (16u * AROWB);
                ah[t][0] = lds32(base);
                ah[t][1] = lds32(base + 8u * AROWB);
                ah[t][2] = lds32(base + 16u);
                ah[t][3] = lds32(base + 8u * AROWB + 16u);
                al[t][0] = lds32(base + ABLK);
                al[t][1] = lds32(base + ABLK + 8u * AROWB);
                al[t][2] = lds32(base + ABLK + 16u);
                al[t][3] = lds32(base + ABLK + 8u * AROWB + 16u);
            }
            unsigned wb = wS + (unsigned)s * 512u;
#pragma unroll
            for (int j = 0; j < 8; j++) {
                uint4 bv = lds128(wb + (unsigned)j * 2048u);
                mma_bf16(acc[0][j], ah[0][0], ah[0][1], ah[0][2], ah[0][3], bv.x, bv.y);
                mma_bf16(acc[0][j], ah[0][0], ah[0][1], ah[0][2], ah[0][3], bv.z, bv.w);
                mma_bf16(acc[0][j], al[0][0], al[0][1], al[0][2], al[0][3], bv.x, bv.y);
                mma_bf16(acc[1][j], ah[1][0], ah[1][1], ah[1][2], ah[1][3], bv.x, bv.y);
                mma_bf16(acc[1][j], ah[1][0], ah[1][1], ah[1][2], ah[1][3], bv.z, bv.w);
                mma_bf16(acc[1][j], al[1][0], al[1][1], al[1][2], al[1][3], bv.x, bv.y);
            }
        }

        if (c + 1 < NCHUNK) cvtSTS(av, (c + 1) & 1);
        __syncthreads();   // STS visible; all reads of W stage (c&1) done
        if (c + 2 < NCHUNK) copyW(c + 2, c & 1);
    }

    // ---- epilogue: clip to [0,1], write concat layout g_x[B,512] ----
    const int rbase = (white ? b : b - NBLK / 2) * 64 + mg * 32 + (l >> 2);
    float* xbase = g_x + (white ? 0 : HID);
#pragma unroll
    for (int t = 0; t < 2; t++) {
        const int r0 = rbase + t * 16;
#pragma unroll
        for (int j = 0; j < 8; j++) {
            const int col = wng * 64 + j * 8 + (l & 3) * 2;
            float2 v0, v1;
            v0.x = fminf(fmaxf(acc[t][j][0], 0.0f), 1.0f);
            v0.y = fminf(fmaxf(acc[t][j][1], 0.0f), 1.0f);
            v1.x = fminf(fmaxf(acc[t][j][2], 0.0f), 1.0f);
            v1.y = fminf(fmaxf(acc[t][j][3], 0.0f), 1.0f);
            *(float2*)(xbase + (size_t)r0 * 512 + col)       = v0;
            *(float2*)(xbase + (size_t)(r0 + 8) * 512 + col) = v1;
        }
    }
}

// ================= kernel 3: MLP 512 -> 32 -> 32 -> 1 (warp per row) =================
__global__ void mlp_kernel(const float* __restrict__ W1, const float* __restrict__ b1,
                           const float* __restrict__ W2, const float* __restrict__ b2,
                           const float* __restrict__ W3, const float* __restrict__ b3,
                           const float* __restrict__ stm, float* __restrict__ out) {
    const int warp = (blockIdx.x * blockDim.x + threadIdx.x) >> 5;
    const int lid  = threadIdx.x & 31;
    if (warp >= B_ROWS) return;
    const float* xr = g_x + (size_t)warp * 512;

    float xv[16];
#pragma unroll
    for (int i = 0; i < 16; i++) xv[i] = xr[lid + 32 * i];

    float h1 = 0.0f;
#pragma unroll
    for (int j = 0; j < 32; j++) {
        const float* wrow = W1 + j * 512;
        float a = 0.0f;
#pragma unroll
        for (int i = 0; i < 16; i++) a += xv[i] * wrow[lid + 32 * i];
#pragma unroll
        for (int off = 16; off > 0; off >>= 1) a += __shfl_xor_sync(0xFFFFFFFFu, a, off);
        a = fmaxf(a + b1[j], 0.0f);
        if (lid == j) h1 = a;
    }

    float a2 = b2[lid];
#pragma unroll
    for (int k = 0; k < 32; k++)
        a2 += __shfl_sync(0xFFFFFFFFu, h1, k) * W2[lid * 32 + k];
    float h2 = fmaxf(a2, 0.0f);

    float v = h2 * W3[lid];
#pragma unroll
    for (int off = 16; off > 0; off >>= 1) v += __shfl_xor_sync(0xFFFFFFFFu, v, off);

    if (lid == 0) out[warp] = (v + b3[0]) * stm[warp];
}

// ================= host launcher =================
extern "C" void kernel_launch(void* const* d_in, const int* in_sizes, int n_in,
                              void* d_out, int out_size) {
    const float* wfeat = (const float*)d_in[0];
    const float* bfeat = (const float*)d_in[1];
    const float* stm   = (const float*)d_in[2];
    const float* Wft   = (const float*)d_in[3];
    const float* W1    = (const float*)d_in[4];
    const float* b1    = (const float*)d_in[5];
    const float* W2    = (const float*)d_in[6];
    const float* b2    = (const float*)d_in[7];
    const float* W3    = (const float*)d_in[8];
    const float* b3    = (const float*)d_in[9];

    static bool attr_set = false;
    if (!attr_set) {
        cudaFuncSetAttribute(ft_gemm_kernel,
                             cudaFuncAttributeMaxDynamicSharedMemorySize, DSMEM_BYTES);
        attr_set = true;
    }

    prep_w_kernel<<<(NCHUNK * 4096) / 256, 256>>>(Wft);
    ft_gemm_kernel<<<NBLK, TPB, DSMEM_BYTES>>>(wfeat, bfeat);
    mlp_kernel<<<(B_ROWS * 32) / 256, 256>>>(W1, b1, W2, b2, W3, b3, stm, (float*)d_out);
}